// round 12
// baseline (speedup 1.0000x reference)
#include <cuda_runtime.h>
#include <math.h>
#include <stdint.h>

// Shapes (fixed by the problem)
#define T_STEPS 32
#define NB      64
#define CDIM    512
#define F1DIM   2048
#define F2DIM   1024
#define F3DIM   512

typedef unsigned long long ull;

// ---------------- scratch (device globals; no allocation allowed) -------------
__device__ float g_F1[T_STEPS * NB * CDIM];
__device__ float g_H1[T_STEPS * NB * F1DIM];
__device__ float g_F2[T_STEPS * NB * F1DIM];
__device__ float g_H2[T_STEPS * NB * F2DIM];
__device__ float g_F3[T_STEPS * NB * F2DIM];
__device__ float g_H3[T_STEPS * NB * F3DIM];

__device__ __forceinline__ float sigmoid_acc(float w) {
    return 1.0f / (1.0f + expf(-w));
}

// ---------------------------------------------------------------------------
// Stage 1 (verbatim from passing R1/R7)
// ---------------------------------------------------------------------------
__global__ void stage1_kernel(const float* __restrict__ x,
                              const float* __restrict__ w_jeff,
                              const float* __restrict__ w_cc,
                              const float* __restrict__ w_sf0,
                              const float* __restrict__ w_sf1)
{
    int gw   = (blockIdx.x * blockDim.x + threadIdx.x) >> 5;
    int lane = threadIdx.x & 31;
    if (gw >= NB * CDIM) return;
    int n = gw / CDIM;
    int c = gw - n * CDIM;

    float wj0 = w_jeff[lane * 2 + 0];
    float wj1 = w_jeff[lane * 2 + 1];
    float wcc = w_cc[lane];
    float d0  = 1.0f - sigmoid_acc(w_sf0[0]);
    float d1  = 1.0f - sigmoid_acc(w_sf1[0]);
    const float invlif = 1.0f / 1.5f;

    float yf0 = 0.f, yf1 = 0.f;
    float v = 0.f, g = 0.f, vI = 0.f, fo = 0.f;

    const float* xb = x + (size_t)n * 2 * CDIM + c;
#pragma unroll
    for (int t = 0; t < T_STEPS; t++) {
        float x0 = xb[(size_t)t * NB * 2 * CDIM];
        float x1 = xb[(size_t)t * NB * 2 * CDIM + CDIM];
        yf0 = 0.5f * yf0 + x0;
        yf1 = 0.5f * yf1 + x1;
        float u = wj0 * yf0 + wj1 * yf1;
        v = v + (u - v) * invlif;
        float s = (v >= 1.0f) ? 1.0f : 0.0f;
        v = (v >= 1.0f) ? 0.0f : v;
        g = d0 * g + s;
        float r = g * wcc;
#pragma unroll
        for (int off = 16; off; off >>= 1)
            r += __shfl_xor_sync(0xffffffffu, r, off);
        vI += r;
        float s1 = (vI >= 1.0f) ? 1.0f : 0.0f;
        vI = (vI >= 1.0f) ? 0.0f : vI;
        fo = d1 * fo + s1;
        if (lane == 0)
            g_F1[((size_t)t * NB + n) * CDIM + c] = fo;
    }
}

// ---------------------------------------------------------------------------
// FP32 GEMM (NT), packed f32x2 FMA, bit-identical sequential-k chains.
// C[m][o] = sum_k A[o][k] * B[m][k]
// Tile: 128 (o) x 128 (m), BK=32, 256 threads, 8(o)x8(m) microtile,
// o-paired accumulators (A operand = direct aligned ull pair from SMEM).
// Double-buffered SMEM, ONE barrier per 32-k chunk.
// ---------------------------------------------------------------------------
#define PADR 132    // floats per k-row (128 + 4)
#define TBUF (32 * PADR)                 // floats per tile buffer
#define SMEM_FLOATS (4 * TBUF)           // A0,A1,B0,B1
#define SMEM_BYTES  (SMEM_FLOATS * 4)    // 67584

#define FMA2(acc, a, b) \
    asm("fma.rn.f32x2 %0, %1, %2, %0;" : "+l"(acc) : "l"(a), "l"(b))
#define PACK_DUP(d, s) \
    asm("mov.b64 %0, {%1, %1};" : "=l"(d) : "f"(s))
#define UNPACK2(lo, hi, v) \
    asm("mov.b64 {%0, %1}, %2;" : "=f"(lo), "=f"(hi) : "l"(v))

__global__ void __launch_bounds__(256, 2)
gemm_x2_kernel(const float* __restrict__ A, const float* __restrict__ B,
               float* __restrict__ C, int Mo, int K)
{
    extern __shared__ float smem[];
    float* Asm = smem;                 // [2][TBUF]
    float* Bsm = smem + 2 * TBUF;      // [2][TBUF]

    int tid = threadIdx.x;
    int tx  = tid & 15;          // m-microtile: m = bn + tx*8
    int ty  = tid >> 4;          // o-microtile: o = bo + ty*8
    int bo  = blockIdx.x * 128;
    int bn  = blockIdx.y * 128;
    int NC  = K / 32;

    // Loader roles (each thread: 4 float4 of A, 4 float4 of B per chunk)
    int row = tid & 127;         // row within tile (o for A, m for B)
    int kf  = tid >> 7;          // 0..1 -> k-cols kf*4 + {0,8,16,24}
    const float* gA = A + (size_t)(bo + row) * K + kf * 4;
    const float* gB = B + (size_t)(bn + row) * K + kf * 4;

    ull acc[4][8];               // [o-pair][m]
#pragma unroll
    for (int i = 0; i < 4; i++)
#pragma unroll
        for (int j = 0; j < 8; j++) acc[i][j] = 0ULL;

    float4 vA[4], vB[4];

    // load chunk 0
#pragma unroll
    for (int p = 0; p < 4; p++) {
        vA[p] = *(const float4*)(gA + p * 8);
        vB[p] = *(const float4*)(gB + p * 8);
    }

    // store chunk 0 into buffer 0 (transpose to [k][row])
    {
        float* cA = &Asm[(kf * 4) * PADR + row];
        float* cB = &Bsm[(kf * 4) * PADR + row];
#pragma unroll
        for (int p = 0; p < 4; p++) {
            float* a = cA + (p * 8) * PADR;
            a[0 * PADR] = vA[p].x; a[1 * PADR] = vA[p].y;
            a[2 * PADR] = vA[p].z; a[3 * PADR] = vA[p].w;
            float* b = cB + (p * 8) * PADR;
            b[0 * PADR] = vB[p].x; b[1 * PADR] = vB[p].y;
            b[2 * PADR] = vB[p].z; b[3 * PADR] = vB[p].w;
        }
    }
    __syncthreads();

    for (int c = 0; c < NC; c++) {
        int buf = c & 1;
        // prefetch chunk c+1 into regs (overlaps compute below)
        if (c + 1 < NC) {
            const float* pA = gA + (c + 1) * 32;
            const float* pB = gB + (c + 1) * 32;
#pragma unroll
            for (int p = 0; p < 4; p++) {
                vA[p] = *(const float4*)(pA + p * 8);
                vB[p] = *(const float4*)(pB + p * 8);
            }
        }

        // compute chunk c (32 k-steps; per-output chain strictly sequential)
        const float* Ab = Asm + buf * TBUF;
        const float* Bb = Bsm + buf * TBUF;
#pragma unroll
        for (int k = 0; k < 32; k++) {
            const float* as = Ab + k * PADR + ty * 8;
            const float* bs = Bb + k * PADR + tx * 8;
            ulonglong2 t0 = *(const ulonglong2*)as;        // o-pairs (0,1),(2,3)
            ulonglong2 t1 = *(const ulonglong2*)(as + 4);  // (4,5),(6,7)
            float4 b0 = *(const float4*)bs;
            float4 b1 = *(const float4*)(bs + 4);
            ull aP[4] = {t0.x, t0.y, t1.x, t1.y};
            ull bb[8];
            PACK_DUP(bb[0], b0.x); PACK_DUP(bb[1], b0.y);
            PACK_DUP(bb[2], b0.z); PACK_DUP(bb[3], b0.w);
            PACK_DUP(bb[4], b1.x); PACK_DUP(bb[5], b1.y);
            PACK_DUP(bb[6], b1.z); PACK_DUP(bb[7], b1.w);
#pragma unroll
            for (int j = 0; j < 8; j++)
#pragma unroll
                for (int i = 0; i < 4; i++)
                    FMA2(acc[i][j], aP[i], bb[j]);
        }

        // store chunk c+1 into the other buffer; ONE barrier per chunk
        if (c + 1 < NC) {
            float* Aw = Asm + (buf ^ 1) * TBUF;
            float* Bw = Bsm + (buf ^ 1) * TBUF;
            float* cA = &Aw[(kf * 4) * PADR + row];
            float* cB = &Bw[(kf * 4) * PADR + row];
#pragma unroll
            for (int p = 0; p < 4; p++) {
                float* a = cA + (p * 8) * PADR;
                a[0 * PADR] = vA[p].x; a[1 * PADR] = vA[p].y;
                a[2 * PADR] = vA[p].z; a[3 * PADR] = vA[p].w;
                float* b = cB + (p * 8) * PADR;
                b[0 * PADR] = vB[p].x; b[1 * PADR] = vB[p].y;
                b[2 * PADR] = vB[p].z; b[3 * PADR] = vB[p].w;
            }
            __syncthreads();
        }
    }

    // Epilogue (R7-proven mapping): row m = bn + tx*8 + j, cols o = bo + ty*8..+7
#pragma unroll
    for (int j = 0; j < 8; j++) {
        float r0, r1, r2, r3, r4, r5, r6, r7;
        UNPACK2(r0, r1, acc[0][j]);
        UNPACK2(r2, r3, acc[1][j]);
        UNPACK2(r4, r5, acc[2][j]);
        UNPACK2(r6, r7, acc[3][j]);
        float* cp = C + (size_t)(bn + tx * 8 + j) * Mo + bo + ty * 8;
        *reinterpret_cast<float4*>(cp + 0) = make_float4(r0, r1, r2, r3);
        *reinterpret_cast<float4*>(cp + 4) = make_float4(r4, r5, r6, r7);
    }
}

// ---------------------------------------------------------------------------
// IFNode + SynapseFilter fused (verbatim from R1/R7).
// ---------------------------------------------------------------------------
__global__ void ifsyn_kernel(const float* __restrict__ H, float* __restrict__ F,
                             const float* __restrict__ w_sf, int Odim)
{
    int idx = blockIdx.x * blockDim.x + threadIdx.x;
    if (idx >= NB * Odim) return;
    int o = idx % Odim;
    int n = idx / Odim;
    float d = 1.0f - sigmoid_acc(w_sf[0]);
    float v = 0.f, f = 0.f;
#pragma unroll
    for (int t = 0; t < T_STEPS; t++) {
        size_t id = ((size_t)t * NB + n) * Odim + o;
        v += H[id];
        float s = (v >= 1.0f) ? 1.0f : 0.0f;
        v = (v >= 1.0f) ? 0.0f : v;
        f = d * f + s;
        F[id] = f;
    }
}

// ---------------------------------------------------------------------------
// Final kernel (verbatim from R1/R7).
// ---------------------------------------------------------------------------
__global__ void final_kernel(const float* __restrict__ Wout,
                             const float* __restrict__ bout,
                             float* __restrict__ out)
{
    int n = blockIdx.x;
    int f = threadIdx.x;
    __shared__ float red[16];
    float v   = 0.f;
    float wf  = Wout[f];
    float acc = 0.f;
    float b   = bout[0];
    int lane = f & 31, wid = f >> 5;
    for (int t = 0; t < T_STEPS; t++) {
        v += g_H3[((size_t)t * NB + n) * F3DIM + f];
        float s = (v >= 1.0f) ? 1.0f : 0.0f;
        v = (v >= 1.0f) ? 0.0f : v;
        float p = wf * s;
#pragma unroll
        for (int off = 16; off; off >>= 1)
            p += __shfl_xor_sync(0xffffffffu, p, off);
        if (lane == 0) red[wid] = p;
        __syncthreads();
        if (f < 16) {
            float q = red[f];
#pragma unroll
            for (int off = 8; off; off >>= 1)
                q += __shfl_xor_sync(0x0000ffffu, q, off);
            if (f == 0) {
                acc += q + b;
                out[t * NB + n] = acc;
            }
        }
        __syncthreads();
    }
}

// ---------------------------------------------------------------------------
extern "C" void kernel_launch(void* const* d_in, const int* in_sizes, int n_in,
                              void* d_out, int out_size)
{
    (void)in_sizes; (void)n_in; (void)out_size;
    const float* x     = (const float*)d_in[0];
    const float* wjeff = (const float*)d_in[1];
    const float* wcc   = (const float*)d_in[2];
    const float* wsf0  = (const float*)d_in[3];
    const float* W1    = (const float*)d_in[4];
    const float* wsf1  = (const float*)d_in[5];
    const float* W2    = (const float*)d_in[6];
    const float* wsf2  = (const float*)d_in[7];
    const float* W3    = (const float*)d_in[8];
    const float* wsf3  = (const float*)d_in[9];
    const float* Wout  = (const float*)d_in[10];
    const float* bout  = (const float*)d_in[11];
    float* out = (float*)d_out;

    float *F1, *H1, *F2, *H2, *F3, *H3;
    cudaGetSymbolAddress((void**)&F1, g_F1);
    cudaGetSymbolAddress((void**)&H1, g_H1);
    cudaGetSymbolAddress((void**)&F2, g_F2);
    cudaGetSymbolAddress((void**)&H2, g_H2);
    cudaGetSymbolAddress((void**)&F3, g_F3);
    cudaGetSymbolAddress((void**)&H3, g_H3);

    cudaFuncSetAttribute(gemm_x2_kernel,
                         cudaFuncAttributeMaxDynamicSharedMemorySize, SMEM_BYTES);

    // Stage 1
    stage1_kernel<<<(NB * CDIM * 32) / 256, 256>>>(x, wjeff, wcc, wsf0, wsf1);

    // Block 1: grid (16,16)=256
    gemm_x2_kernel<<<dim3(F1DIM / 128, (T_STEPS * NB) / 128), 256, SMEM_BYTES>>>(W1, F1, H1, F1DIM, CDIM);
    ifsyn_kernel<<<(NB * F1DIM + 255) / 256, 256>>>(H1, F2, wsf2, F1DIM);

    // Block 2: grid (8,16)=128
    gemm_x2_kernel<<<dim3(F2DIM / 128, (T_STEPS * NB) / 128), 256, SMEM_BYTES>>>(W2, F2, H2, F2DIM, F1DIM);
    ifsyn_kernel<<<(NB * F2DIM + 255) / 256, 256>>>(H2, F3, wsf3, F2DIM);

    // Block 3: grid (4,16)=64
    gemm_x2_kernel<<<dim3(F3DIM / 128, (T_STEPS * NB) / 128), 256, SMEM_BYTES>>>(W3, F3, H3, F3DIM, F2DIM);

    // Final linear + NonSpikingIF cumsum
    final_kernel<<<NB, F3DIM>>>(Wout, bout, out);
}

// round 13
// speedup vs baseline: 1.1072x; 1.1072x over previous
#include <cuda_runtime.h>
#include <math.h>
#include <stdint.h>

// Shapes (fixed by the problem)
#define T_STEPS 32
#define NB      64
#define CDIM    512
#define F1DIM   2048
#define F2DIM   1024
#define F3DIM   512

typedef unsigned long long ull;

// ---------------- scratch (device globals; no allocation allowed) -------------
__device__ float g_F1[T_STEPS * NB * CDIM];
__device__ float g_H1[T_STEPS * NB * F1DIM];
__device__ float g_F2[T_STEPS * NB * F1DIM];
__device__ float g_H2[T_STEPS * NB * F2DIM];
__device__ float g_F3[T_STEPS * NB * F2DIM];
__device__ float g_H3[T_STEPS * NB * F3DIM];

__device__ __forceinline__ float sigmoid_acc(float w) {
    return 1.0f / (1.0f + expf(-w));
}

// ---------------------------------------------------------------------------
// Stage 1 (verbatim from passing R1/R7)
// ---------------------------------------------------------------------------
__global__ void stage1_kernel(const float* __restrict__ x,
                              const float* __restrict__ w_jeff,
                              const float* __restrict__ w_cc,
                              const float* __restrict__ w_sf0,
                              const float* __restrict__ w_sf1)
{
    int gw   = (blockIdx.x * blockDim.x + threadIdx.x) >> 5;
    int lane = threadIdx.x & 31;
    if (gw >= NB * CDIM) return;
    int n = gw / CDIM;
    int c = gw - n * CDIM;

    float wj0 = w_jeff[lane * 2 + 0];
    float wj1 = w_jeff[lane * 2 + 1];
    float wcc = w_cc[lane];
    float d0  = 1.0f - sigmoid_acc(w_sf0[0]);
    float d1  = 1.0f - sigmoid_acc(w_sf1[0]);
    const float invlif = 1.0f / 1.5f;

    float yf0 = 0.f, yf1 = 0.f;
    float v = 0.f, g = 0.f, vI = 0.f, fo = 0.f;

    const float* xb = x + (size_t)n * 2 * CDIM + c;
#pragma unroll
    for (int t = 0; t < T_STEPS; t++) {
        float x0 = xb[(size_t)t * NB * 2 * CDIM];
        float x1 = xb[(size_t)t * NB * 2 * CDIM + CDIM];
        yf0 = 0.5f * yf0 + x0;
        yf1 = 0.5f * yf1 + x1;
        float u = wj0 * yf0 + wj1 * yf1;
        v = v + (u - v) * invlif;
        float s = (v >= 1.0f) ? 1.0f : 0.0f;
        v = (v >= 1.0f) ? 0.0f : v;
        g = d0 * g + s;
        float r = g * wcc;
#pragma unroll
        for (int off = 16; off; off >>= 1)
            r += __shfl_xor_sync(0xffffffffu, r, off);
        vI += r;
        float s1 = (vI >= 1.0f) ? 1.0f : 0.0f;
        vI = (vI >= 1.0f) ? 0.0f : vI;
        fo = d1 * fo + s1;
        if (lane == 0)
            g_F1[((size_t)t * NB + n) * CDIM + c] = fo;
    }
}

// ---------------------------------------------------------------------------
// FP32 GEMM (NT), packed f32x2 FMA, bit-identical sequential-k chains.
// C[m][o] = sum_k A[o][k] * B[m][k]
// Tile: 64 (o) x 128 (m), BK=32, 256 threads, microtile 4(o) x 8(m),
// m-paired accumulators. Double-buffered SMEM, ONE barrier per chunk,
// EXPLICIT fragment double-buffering inside the k-loop (hide LDS latency).
// ---------------------------------------------------------------------------
#define PADA 68     // floats per k-row of As (64 o + 4)
#define PADB 132    // floats per k-row of Bs (128 m + 4)
#define ABUF (32 * PADA)
#define BBUF (32 * PADB)
#define SMEM_FLOATS (2 * ABUF + 2 * BBUF)
#define SMEM_BYTES  (SMEM_FLOATS * 4)   // 51200

#define FMA2(acc, a, b) \
    asm("fma.rn.f32x2 %0, %1, %2, %0;" : "+l"(acc) : "l"(a), "l"(b))
#define PACK_DUP(d, s) \
    asm("mov.b64 %0, {%1, %1};" : "=l"(d) : "f"(s))
#define UNPACK2(lo, hi, v) \
    asm("mov.b64 {%0, %1}, %2;" : "=f"(lo), "=f"(hi) : "l"(v))

__global__ void __launch_bounds__(256, 2)
gemm_x2_kernel(const float* __restrict__ A, const float* __restrict__ B,
               float* __restrict__ C, int Mo, int K)
{
    extern __shared__ float smem[];
    float* Asm = smem;                    // [2][32*PADA]
    float* Bsm = smem + 2 * ABUF;         // [2][32*PADB]

    int tid = threadIdx.x;
    int ty  = tid & 15;          // o-microtile: o = bo + ty*4
    int tx  = tid >> 4;          // m-microtile: m = bn + tx*8
    int bo  = blockIdx.x * 64;
    int bn  = blockIdx.y * 128;
    int NC  = K / 32;

    // Loader roles (BK=32)
    int ao = tid & 63;           // A row (o);  cols: af*4 and af*4+16
    int af = tid >> 6;           // 0..3
    const float* gA = A + (size_t)(bo + ao) * K + af * 4;
    int bm = tid & 127;          // B row (m);  cols: bf*4 + {0,8,16,24}
    int bf = tid >> 7;           // 0..1
    const float* gB = B + (size_t)(bn + bm) * K + bf * 4;

    ull acc[4][4];               // [o][m-pair]
#pragma unroll
    for (int i = 0; i < 4; i++)
#pragma unroll
        for (int j = 0; j < 4; j++) acc[i][j] = 0ULL;

    float4 vA0, vA1, vB0, vB1, vB2, vB3;

    // load chunk 0
    vA0 = *(const float4*)(gA);
    vA1 = *(const float4*)(gA + 16);
    vB0 = *(const float4*)(gB);
    vB1 = *(const float4*)(gB + 8);
    vB2 = *(const float4*)(gB + 16);
    vB3 = *(const float4*)(gB + 24);

    // store chunk 0 into buffer 0 (transpose to [k][row])
    {
        float* cA = &Asm[(af * 4) * PADA + ao];
        cA[0 * PADA] = vA0.x; cA[1 * PADA] = vA0.y;
        cA[2 * PADA] = vA0.z; cA[3 * PADA] = vA0.w;
        float* cA2 = cA + 16 * PADA;
        cA2[0 * PADA] = vA1.x; cA2[1 * PADA] = vA1.y;
        cA2[2 * PADA] = vA1.z; cA2[3 * PADA] = vA1.w;
        float* cB = &Bsm[(bf * 4) * PADB + bm];
        cB[0 * PADB] = vB0.x; cB[1 * PADB] = vB0.y;
        cB[2 * PADB] = vB0.z; cB[3 * PADB] = vB0.w;
        float* p = cB + 8 * PADB;
        p[0 * PADB] = vB1.x; p[1 * PADB] = vB1.y;
        p[2 * PADB] = vB1.z; p[3 * PADB] = vB1.w;
        p = cB + 16 * PADB;
        p[0 * PADB] = vB2.x; p[1 * PADB] = vB2.y;
        p[2 * PADB] = vB2.z; p[3 * PADB] = vB2.w;
        p = cB + 24 * PADB;
        p[0 * PADB] = vB3.x; p[1 * PADB] = vB3.y;
        p[2 * PADB] = vB3.z; p[3 * PADB] = vB3.w;
    }
    __syncthreads();

    for (int c = 0; c < NC; c++) {
        int buf = c & 1;
        // prefetch chunk c+1 into regs (overlaps compute below)
        if (c + 1 < NC) {
            const float* pA = gA + (c + 1) * 32;
            const float* pB = gB + (c + 1) * 32;
            vA0 = *(const float4*)(pA);
            vA1 = *(const float4*)(pA + 16);
            vB0 = *(const float4*)(pB);
            vB1 = *(const float4*)(pB + 8);
            vB2 = *(const float4*)(pB + 16);
            vB3 = *(const float4*)(pB + 24);
        }

        // compute chunk c (32 k-steps), fragments double-buffered in regs
        const float* Ab = Asm + buf * ABUF;
        const float* Bb = Bsm + buf * BBUF;
        {
            float4     avf[2];
            ulonglong2 u0f[2], u1f[2];
            avf[0] = *(const float4*)(Ab + ty * 4);
            u0f[0] = *(const ulonglong2*)(Bb + tx * 8);
            u1f[0] = *(const ulonglong2*)(Bb + tx * 8 + 4);
#pragma unroll
            for (int k = 0; k < 32; k++) {
                int cur = k & 1;
                if (k < 31) {
                    const float* asn = Ab + (k + 1) * PADA + ty * 4;
                    const float* bsn = Bb + (k + 1) * PADB + tx * 8;
                    avf[cur ^ 1] = *(const float4*)asn;
                    u0f[cur ^ 1] = *(const ulonglong2*)bsn;
                    u1f[cur ^ 1] = *(const ulonglong2*)(bsn + 4);
                }
                ull aD[4];
                PACK_DUP(aD[0], avf[cur].x); PACK_DUP(aD[1], avf[cur].y);
                PACK_DUP(aD[2], avf[cur].z); PACK_DUP(aD[3], avf[cur].w);
                ull bP[4] = {u0f[cur].x, u0f[cur].y, u1f[cur].x, u1f[cur].y};
#pragma unroll
                for (int i = 0; i < 4; i++)
#pragma unroll
                    for (int j = 0; j < 4; j++)
                        FMA2(acc[i][j], aD[i], bP[j]);
            }
        }

        // store chunk c+1 into the other buffer; ONE barrier per chunk
        if (c + 1 < NC) {
            float* Aw = Asm + (buf ^ 1) * ABUF;
            float* Bw = Bsm + (buf ^ 1) * BBUF;
            float* cA = &Aw[(af * 4) * PADA + ao];
            cA[0 * PADA] = vA0.x; cA[1 * PADA] = vA0.y;
            cA[2 * PADA] = vA0.z; cA[3 * PADA] = vA0.w;
            float* cA2 = cA + 16 * PADA;
            cA2[0 * PADA] = vA1.x; cA2[1 * PADA] = vA1.y;
            cA2[2 * PADA] = vA1.z; cA2[3 * PADA] = vA1.w;
            float* cB = &Bw[(bf * 4) * PADB + bm];
            cB[0 * PADB] = vB0.x; cB[1 * PADB] = vB0.y;
            cB[2 * PADB] = vB0.z; cB[3 * PADB] = vB0.w;
            float* p = cB + 8 * PADB;
            p[0 * PADB] = vB1.x; p[1 * PADB] = vB1.y;
            p[2 * PADB] = vB1.z; p[3 * PADB] = vB1.w;
            p = cB + 16 * PADB;
            p[0 * PADB] = vB2.x; p[1 * PADB] = vB2.y;
            p[2 * PADB] = vB2.z; p[3 * PADB] = vB2.w;
            p = cB + 24 * PADB;
            p[0 * PADB] = vB3.x; p[1 * PADB] = vB3.y;
            p[2 * PADB] = vB3.z; p[3 * PADB] = vB3.w;
            __syncthreads();
        }
    }

    // Epilogue: acc[i][j] = (C[m][o], C[m+1][o]), m = bn+tx*8+j*2, o = bo+ty*4+i
#pragma unroll
    for (int j = 0; j < 4; j++) {
        float lo0, hi0, lo1, hi1, lo2, hi2, lo3, hi3;
        UNPACK2(lo0, hi0, acc[0][j]);
        UNPACK2(lo1, hi1, acc[1][j]);
        UNPACK2(lo2, hi2, acc[2][j]);
        UNPACK2(lo3, hi3, acc[3][j]);
        int m = bn + tx * 8 + j * 2;
        float* cp0 = C + (size_t)m * Mo + bo + ty * 4;
        float* cp1 = C + (size_t)(m + 1) * Mo + bo + ty * 4;
        *reinterpret_cast<float4*>(cp0) = make_float4(lo0, lo1, lo2, lo3);
        *reinterpret_cast<float4*>(cp1) = make_float4(hi0, hi1, hi2, hi3);
    }
}

// ---------------------------------------------------------------------------
// IFNode + SynapseFilter fused (verbatim from R1/R7).
// ---------------------------------------------------------------------------
__global__ void ifsyn_kernel(const float* __restrict__ H, float* __restrict__ F,
                             const float* __restrict__ w_sf, int Odim)
{
    int idx = blockIdx.x * blockDim.x + threadIdx.x;
    if (idx >= NB * Odim) return;
    int o = idx % Odim;
    int n = idx / Odim;
    float d = 1.0f - sigmoid_acc(w_sf[0]);
    float v = 0.f, f = 0.f;
#pragma unroll
    for (int t = 0; t < T_STEPS; t++) {
        size_t id = ((size_t)t * NB + n) * Odim + o;
        v += H[id];
        float s = (v >= 1.0f) ? 1.0f : 0.0f;
        v = (v >= 1.0f) ? 0.0f : v;
        f = d * f + s;
        F[id] = f;
    }
}

// ---------------------------------------------------------------------------
// Final kernel (verbatim from R1/R7).
// ---------------------------------------------------------------------------
__global__ void final_kernel(const float* __restrict__ Wout,
                             const float* __restrict__ bout,
                             float* __restrict__ out)
{
    int n = blockIdx.x;
    int f = threadIdx.x;
    __shared__ float red[16];
    float v   = 0.f;
    float wf  = Wout[f];
    float acc = 0.f;
    float b   = bout[0];
    int lane = f & 31, wid = f >> 5;
    for (int t = 0; t < T_STEPS; t++) {
        v += g_H3[((size_t)t * NB + n) * F3DIM + f];
        float s = (v >= 1.0f) ? 1.0f : 0.0f;
        v = (v >= 1.0f) ? 0.0f : v;
        float p = wf * s;
#pragma unroll
        for (int off = 16; off; off >>= 1)
            p += __shfl_xor_sync(0xffffffffu, p, off);
        if (lane == 0) red[wid] = p;
        __syncthreads();
        if (f < 16) {
            float q = red[f];
#pragma unroll
            for (int off = 8; off; off >>= 1)
                q += __shfl_xor_sync(0x0000ffffu, q, off);
            if (f == 0) {
                acc += q + b;
                out[t * NB + n] = acc;
            }
        }
        __syncthreads();
    }
}

// ---------------------------------------------------------------------------
extern "C" void kernel_launch(void* const* d_in, const int* in_sizes, int n_in,
                              void* d_out, int out_size)
{
    (void)in_sizes; (void)n_in; (void)out_size;
    const float* x     = (const float*)d_in[0];
    const float* wjeff = (const float*)d_in[1];
    const float* wcc   = (const float*)d_in[2];
    const float* wsf0  = (const float*)d_in[3];
    const float* W1    = (const float*)d_in[4];
    const float* wsf1  = (const float*)d_in[5];
    const float* W2    = (const float*)d_in[6];
    const float* wsf2  = (const float*)d_in[7];
    const float* W3    = (const float*)d_in[8];
    const float* wsf3  = (const float*)d_in[9];
    const float* Wout  = (const float*)d_in[10];
    const float* bout  = (const float*)d_in[11];
    float* out = (float*)d_out;

    float *F1, *H1, *F2, *H2, *F3, *H3;
    cudaGetSymbolAddress((void**)&F1, g_F1);
    cudaGetSymbolAddress((void**)&H1, g_H1);
    cudaGetSymbolAddress((void**)&F2, g_F2);
    cudaGetSymbolAddress((void**)&H2, g_H2);
    cudaGetSymbolAddress((void**)&F3, g_F3);
    cudaGetSymbolAddress((void**)&H3, g_H3);

    cudaFuncSetAttribute(gemm_x2_kernel,
                         cudaFuncAttributeMaxDynamicSharedMemorySize, SMEM_BYTES);

    // Stage 1
    stage1_kernel<<<(NB * CDIM * 32) / 256, 256>>>(x, wjeff, wcc, wsf0, wsf1);

    // Block 1: grid (32,16)=512
    gemm_x2_kernel<<<dim3(F1DIM / 64, (T_STEPS * NB) / 128), 256, SMEM_BYTES>>>(W1, F1, H1, F1DIM, CDIM);
    ifsyn_kernel<<<(NB * F1DIM + 255) / 256, 256>>>(H1, F2, wsf2, F1DIM);

    // Block 2: grid (16,16)=256
    gemm_x2_kernel<<<dim3(F2DIM / 64, (T_STEPS * NB) / 128), 256, SMEM_BYTES>>>(W2, F2, H2, F2DIM, F1DIM);
    ifsyn_kernel<<<(NB * F2DIM + 255) / 256, 256>>>(H2, F3, wsf3, F2DIM);

    // Block 3: grid (8,16)=128
    gemm_x2_kernel<<<dim3(F3DIM / 64, (T_STEPS * NB) / 128), 256, SMEM_BYTES>>>(W3, F3, H3, F3DIM, F2DIM);

    // Final linear + NonSpikingIF cumsum
    final_kernel<<<NB, F3DIM>>>(Wout, bout, out);
}